// round 6
// baseline (speedup 1.0000x reference)
#include <cuda_runtime.h>
#include <cstdint>

// x: (B=8, H=256, W=256, C=64) fp32, WIN=16, half=8
// out: (B, 961, 16*16*64) fp32, partition order (0,0),(0,8),(8,0),(8,8)
// windows per partition: 256, 240, 240, 225 -> 961 per batch (7688 total)
//
// R2 data path (16 front-batched LDG.128 + 16 streaming STG.128 per window)
// in a PERSISTENT grid-stride form: exactly 2 CTAs/SM * 148 SMs = 296 blocks,
// each handling ~26 windows. Removes ~26 wave transitions + launch tail and
// lets ptxas overlap window k+1 loads with window k stores.

#define NPB 961
#define NWIN (8 * NPB)            // 7688
#define NBLK 296                  // 148 SMs * 2 CTAs/SM
#define ROW_F4 (256 * 64 / 4)     // float4 per input image row = 4096

__global__ void __launch_bounds__(256, 2)
partition_kernel(const float4* __restrict__ x, float4* __restrict__ out)
{
    const int t = threadIdx.x;    // 0..255: one float4 of each 4KB window-row

    for (int blk = blockIdx.x; blk < NWIN; blk += NBLK) {
        const int b = blk / NPB;
        const int p = blk - b * NPB;

        int r0, c0, nc, base;
        if (p < 256)      { r0 = 0; c0 = 0; nc = 16; base = 0;   }
        else if (p < 496) { r0 = 0; c0 = 8; nc = 15; base = 256; }
        else if (p < 736) { r0 = 8; c0 = 0; nc = 16; base = 496; }
        else              { r0 = 8; c0 = 8; nc = 15; base = 736; }

        const int q  = p - base;
        const int wr = q / nc;
        const int wc = q - wr * nc;
        const int row0 = r0 + wr * 16;
        const int col0 = c0 + wc * 16;

        const float4* __restrict__ src = x
            + (size_t)(b * 256 + row0) * ROW_F4 + (size_t)col0 * 16;
        float4* __restrict__ dst = out + (size_t)blk * (16 * 16 * 64 / 4);

        // Front-batch all 16 independent LDG.128s, then drain with
        // 16 streaming STG.128s (keeps reused input slice in L2).
        float4 v[16];
#pragma unroll
        for (int i = 0; i < 16; ++i)
            v[i] = __ldg(&src[(size_t)i * ROW_F4 + t]);
#pragma unroll
        for (int i = 0; i < 16; ++i)
            __stcs(&dst[i * 256 + t], v[i]);
    }
}

extern "C" void kernel_launch(void* const* d_in, const int* in_sizes, int n_in,
                              void* d_out, int out_size)
{
    const float4* x = (const float4*)d_in[0];
    float4* out = (float4*)d_out;
    partition_kernel<<<NBLK, 256>>>(x, out);
}